// round 11
// baseline (speedup 1.0000x reference)
#include <cuda_runtime.h>
#include <cuda_fp16.h>
#include <cstdint>

#define BB 32768
#define II 256
#define HH 512
#define KK 768        // I + H, single fp16 pass
#define NN 2048       // 4 * H gates

__device__ __half g_A[(size_t)BB * KK];   // [B][K]  fp16
__device__ __half g_W[(size_t)NN * KK];   // [N][K]  fp16, N interleaved (u,g)
__device__ float g_bias[NN];

// ---------------------------------------------------------------------------
// PTX helpers
// ---------------------------------------------------------------------------
__device__ __forceinline__ void cp_async16(uint32_t saddr, const void* gaddr) {
    asm volatile("cp.async.cg.shared.global [%0], [%1], 16;\n"
                 :: "r"(saddr), "l"(gaddr));
}
__device__ __forceinline__ void ldsm_x4(uint32_t* r, uint32_t addr) {
    asm volatile("ldmatrix.sync.aligned.m8n8.x4.shared.b16 {%0,%1,%2,%3}, [%4];\n"
                 : "=r"(r[0]), "=r"(r[1]), "=r"(r[2]), "=r"(r[3]) : "r"(addr));
}
// fp16-accumulator mma: D(fp16x2 x2) = A*B + C. 2x tensor rate vs f32 acc.
__device__ __forceinline__ void mma16816h(uint32_t* d, const uint32_t* a,
                                          uint32_t b0, uint32_t b1,
                                          uint32_t c0, uint32_t c1) {
    asm volatile(
        "mma.sync.aligned.m16n8k16.row.col.f16.f16.f16.f16 "
        "{%0,%1}, {%2,%3,%4,%5}, {%6,%7}, {%8,%9};\n"
        : "=r"(d[0]), "=r"(d[1])
        : "r"(a[0]), "r"(a[1]), "r"(a[2]), "r"(a[3]),
          "r"(b0), "r"(b1), "r"(c0), "r"(c1));
}

// ---------------------------------------------------------------------------
// Merged prep kernel (fp16 A, W, bias). Gate cols interleaved:
// out col n <-> (u=n>>2, g=n&3); src row = g*H+u.
// ---------------------------------------------------------------------------
#define NB_A (BB * (KK / 4) / 256)     // 24576
#define NB_W (NN * (KK / 4) / 256)     // 1536

__global__ void prep_all(const float* __restrict__ x, const float* __restrict__ h,
                         const float* __restrict__ Wx, const float* __restrict__ bx,
                         const float* __restrict__ Wh, const float* __restrict__ bh) {
    int bidx = blockIdx.x;
    if (bidx < NB_A) {
        int idx = bidx * 256 + threadIdx.x;
        int b = idx / (KK / 4), kc = idx % (KK / 4);
        int k0 = kc * 4;
        float4 v;
        if (k0 < II) v = *(const float4*)(x + (size_t)b * II + k0);
        else         v = *(const float4*)(h + (size_t)b * HH + (k0 - II));
        union { __half h[4]; uint2 u2; } p;
        p.h[0] = __float2half_rn(v.x); p.h[1] = __float2half_rn(v.y);
        p.h[2] = __float2half_rn(v.z); p.h[3] = __float2half_rn(v.w);
        *(uint2*)(g_A + (size_t)b * KK + k0) = p.u2;
    } else {
        int idx = (bidx - NB_A) * 256 + threadIdx.x;
        int n = idx / (KK / 4), kc = idx % (KK / 4);
        int u = n >> 2, g = n & 3, src = g * HH + u;
        int k0 = kc * 4;
        float4 v;
        if (k0 < II) v = *(const float4*)(Wx + (size_t)src * II + k0);
        else         v = *(const float4*)(Wh + (size_t)src * HH + (k0 - II));
        union { __half h[4]; uint2 u2; } p;
        p.h[0] = __float2half_rn(v.x); p.h[1] = __float2half_rn(v.y);
        p.h[2] = __float2half_rn(v.z); p.h[3] = __float2half_rn(v.w);
        *(uint2*)(g_W + (size_t)n * KK + k0) = p.u2;
        if (kc == 0) g_bias[n] = bx[src] + bh[src];
    }
}

// ---------------------------------------------------------------------------
// Fused GEMM + LSTM epilogue. (R8 structure: syncthreads 3-stage ring,
// stagger, late prefetch.) NEW: fp16 accumulators within each K64 chunk
// (2x tensor rate), promoted to fp32 master accumulators once per chunk.
// CTA tile 128x128; 8 warps 4x2; warp tile 32x64. 128B rows, XOR-8 swizzle.
// 2 CTAs/SM.
// ---------------------------------------------------------------------------
#define KCH 64
#define NK  (KK / KCH)        // 12
#define ROWB 128              // bytes per smem row (64 halves, swizzled)
#define ASTG (128 * ROWB)     // 16384 per tile
#define STG  (2 * ASTG)       // 32768 per stage (A + B)
#define NSTAGE 3
#define SMEM_DYN (NSTAGE * STG)   // 98304

__global__ void __launch_bounds__(256, 2)
lstm_gemm(const float* __restrict__ c_in, float* __restrict__ out) {
    extern __shared__ __align__(16) unsigned char smem[];
    __shared__ float bias_s[128];

    const int tid  = threadIdx.x;
    const int warp = tid >> 5, lane = tid & 31;
    const int wm = warp >> 1, wn = warp & 1;       // 4x2 warp grid
    const int mBase = blockIdx.y * 128;
    const int nBase = blockIdx.x * 128;

    const uint32_t sbase = (uint32_t)__cvta_generic_to_shared(smem);
    if (tid < 128) bias_s[tid] = g_bias[nBase + tid];

    float acc[2][8][4];
#pragma unroll
    for (int mi = 0; mi < 2; mi++)
#pragma unroll
        for (int ni = 0; ni < 8; ni++)
#pragma unroll
            for (int d = 0; d < 4; d++) acc[mi][ni][d] = 0.f;

    const __half* gAp = g_A + (size_t)mBase * KK;
    const __half* gWp = g_W + (size_t)nBase * KK;

    // A: 128 rows x 8 chunks(16B) = 1024 chunks; 4 per thread. B same.
    auto load_stage = [&](int kt, int stage) {
        uint32_t so = sbase + stage * STG;
#pragma unroll
        for (int j = 0; j < 4; j++) {
            int idx = tid + j * 256;
            int row = idx >> 3, ch = idx & 7;
            cp_async16(so + row * ROWB + ((ch ^ (row & 7)) << 4),
                       gAp + (size_t)row * KK + kt * KCH + ch * 8);
        }
#pragma unroll
        for (int j = 0; j < 4; j++) {
            int idx = tid + j * 256;
            int row = idx >> 3, ch = idx & 7;
            cp_async16(so + ASTG + row * ROWB + ((ch ^ (row & 7)) << 4),
                       gWp + (size_t)row * KK + kt * KCH + ch * 8);
        }
    };

    load_stage(0, 0);
    asm volatile("cp.async.commit_group;\n");
    load_stage(1, 1);
    asm volatile("cp.async.commit_group;\n");

    const int koff = warp & 3;     // stagger k16-step start across SMSP warps

    for (int kt = 0; kt < NK; kt++) {
        if (kt < NK - 1) asm volatile("cp.async.wait_group 1;\n");
        else             asm volatile("cp.async.wait_group 0;\n");
        __syncthreads();

        const uint32_t so = sbase + (kt % NSTAGE) * STG;
        uint32_t acc16[2][8][2];               // chunk-local fp16 accumulators
#pragma unroll
        for (int ksi = 0; ksi < 4; ksi++) {    // four k16 steps per chunk
            const int ks = (ksi + koff) & 3;   // per-warp staggered order
            uint32_t a_regs[2][4];
#pragma unroll
            for (int mi = 0; mi < 2; mi++) {
                int row = wm * 32 + mi * 16 + (lane & 15);
                int ch  = ks * 2 + (lane >> 4);
                ldsm_x4(a_regs[mi], so + row * ROWB + ((ch ^ (row & 7)) << 4));
            }
#pragma unroll
            for (int p = 0; p < 4; p++) {      // each x4 covers two n-tiles
                int nrow = wn * 64 + p * 16 + ((lane >> 4) << 3) + (lane & 7);
                int ch   = ks * 2 + ((lane >> 3) & 1);
                uint32_t r[4];
                ldsm_x4(r, so + ASTG + nrow * ROWB + ((ch ^ (nrow & 7)) << 4));
#pragma unroll
                for (int mi = 0; mi < 2; mi++) {
                    if (ksi == 0) {
                        mma16816h(acc16[mi][2 * p],     a_regs[mi], r[0], r[1], 0u, 0u);
                        mma16816h(acc16[mi][2 * p + 1], a_regs[mi], r[2], r[3], 0u, 0u);
                    } else {
                        mma16816h(acc16[mi][2 * p],     a_regs[mi], r[0], r[1],
                                  acc16[mi][2 * p][0], acc16[mi][2 * p][1]);
                        mma16816h(acc16[mi][2 * p + 1], a_regs[mi], r[2], r[3],
                                  acc16[mi][2 * p + 1][0], acc16[mi][2 * p + 1][1]);
                    }
                }
            }

            // Prefetch next+1 stage AFTER the first k16 step (R8 placement).
            if (ksi == 0 && kt + 2 < NK) {
                load_stage(kt + 2, (kt + 2) % NSTAGE);
                asm volatile("cp.async.commit_group;\n");
            }
        }

        // Promote chunk-local fp16 accumulators into fp32 master accumulators.
#pragma unroll
        for (int mi = 0; mi < 2; mi++)
#pragma unroll
            for (int ni = 0; ni < 8; ni++) {
                float2 lo = __half22float2(*(__half2*)&acc16[mi][ni][0]);
                float2 hi = __half22float2(*(__half2*)&acc16[mi][ni][1]);
                acc[mi][ni][0] += lo.x;
                acc[mi][ni][1] += lo.y;
                acc[mi][ni][2] += hi.x;
                acc[mi][ni][3] += hi.y;
            }
    }

    // ---- Fused LSTM epilogue (two 64-row phases through smem) ----
    float* egs = (float*)smem;                      // [64][130] = 33280 B
#pragma unroll 1
    for (int half = 0; half < 2; half++) {
        __syncthreads();
        if ((wm >> 1) == half) {
            int rb = (wm & 1) * 32;
#pragma unroll
            for (int mi = 0; mi < 2; mi++)
#pragma unroll
                for (int ni = 0; ni < 8; ni++) {
                    int r = rb + mi * 16 + (lane >> 2);
                    int col = wn * 64 + ni * 8 + ((lane & 3) << 1);
                    egs[r * 130 + col]           = acc[mi][ni][0];
                    egs[r * 130 + col + 1]       = acc[mi][ni][1];
                    egs[(r + 8) * 130 + col]     = acc[mi][ni][2];
                    egs[(r + 8) * 130 + col + 1] = acc[mi][ni][3];
                }
        }
        __syncthreads();
#pragma unroll
        for (int i = 0; i < 8; i++) {
            int item = tid + i * 256;               // 2048 (row, hidden) items
            int ml = item >> 5, u = item & 31;
            float gi = egs[ml * 130 + 4 * u]     + bias_s[4 * u];
            float gf = egs[ml * 130 + 4 * u + 1] + bias_s[4 * u + 1];
            float go = egs[ml * 130 + 4 * u + 2] + bias_s[4 * u + 2];
            float gc = egs[ml * 130 + 4 * u + 3] + bias_s[4 * u + 3];
            float it = 1.f / (1.f + __expf(-gi));
            float ft = 1.f / (1.f + __expf(-gf));
            float ot = 1.f / (1.f + __expf(-go));
            float tc = 1.f - 2.f / (1.f + __expf(2.f * gc));   // tanh via MUFU
            int mg = mBase + half * 64 + ml;
            int ug = (nBase >> 2) + u;
            float cv = c_in[(size_t)mg * HH + ug];
            float ct = ft * cv + it * tc;
            float ht = ot * (1.f - 2.f / (1.f + __expf(2.f * ct)));
            out[(size_t)mg * HH + ug] = ct;
            out[(size_t)BB * HH + (size_t)mg * HH + ug] = ht;
        }
    }
}

// ---------------------------------------------------------------------------
extern "C" void kernel_launch(void* const* d_in, const int* in_sizes, int n_in,
                              void* d_out, int out_size) {
    (void)in_sizes; (void)n_in; (void)out_size;
    const float* x  = (const float*)d_in[0];
    const float* h  = (const float*)d_in[1];
    const float* c  = (const float*)d_in[2];
    const float* Wx = (const float*)d_in[3];
    const float* bx = (const float*)d_in[4];
    const float* Wh = (const float*)d_in[5];
    const float* bh = (const float*)d_in[6];
    float* out = (float*)d_out;

    cudaFuncSetAttribute(lstm_gemm, cudaFuncAttributeMaxDynamicSharedMemorySize, SMEM_DYN);

    prep_all<<<NB_A + NB_W, 256>>>(x, h, Wx, bx, Wh, bh);
    lstm_gemm<<<dim3(NN / 128, BB / 128), 256, SMEM_DYN>>>(c, out);
}

// round 12
// speedup vs baseline: 1.3525x; 1.3525x over previous
#include <cuda_runtime.h>
#include <cuda_fp16.h>
#include <cstdint>

#define BB 32768
#define II 256
#define HH 512
#define KK 768        // I + H, single fp16 pass
#define NN 2048       // 4 * H gates

__device__ __half g_A[(size_t)BB * KK];   // [B][K]  fp16
__device__ __half g_W[(size_t)NN * KK];   // [N][K]  fp16, N interleaved (u,g)
__device__ float g_bias[NN];

// ---------------------------------------------------------------------------
// PTX helpers
// ---------------------------------------------------------------------------
__device__ __forceinline__ void cp_async16(uint32_t saddr, const void* gaddr) {
    asm volatile("cp.async.cg.shared.global [%0], [%1], 16;\n"
                 :: "r"(saddr), "l"(gaddr));
}
__device__ __forceinline__ void ldsm_x4(uint32_t* r, uint32_t addr) {
    asm volatile("ldmatrix.sync.aligned.m8n8.x4.shared.b16 {%0,%1,%2,%3}, [%4];\n"
                 : "=r"(r[0]), "=r"(r[1]), "=r"(r[2]), "=r"(r[3]) : "r"(addr));
}
__device__ __forceinline__ void mma16816(float* d, const uint32_t* a, const uint32_t* b) {
    asm volatile(
        "mma.sync.aligned.m16n8k16.row.col.f32.f16.f16.f32 "
        "{%0,%1,%2,%3}, {%4,%5,%6,%7}, {%8,%9}, {%0,%1,%2,%3};\n"
        : "+f"(d[0]), "+f"(d[1]), "+f"(d[2]), "+f"(d[3])
        : "r"(a[0]), "r"(a[1]), "r"(a[2]), "r"(a[3]), "r"(b[0]), "r"(b[1]));
}

// ---------------------------------------------------------------------------
// Merged prep kernel (fp16 A, W, bias). Gate cols interleaved:
// out col n <-> (u=n>>2, g=n&3); src row = g*H+u.
// ---------------------------------------------------------------------------
#define NB_A (BB * (KK / 4) / 256)     // 24576
#define NB_W (NN * (KK / 4) / 256)     // 1536

__global__ void prep_all(const float* __restrict__ x, const float* __restrict__ h,
                         const float* __restrict__ Wx, const float* __restrict__ bx,
                         const float* __restrict__ Wh, const float* __restrict__ bh) {
    int bidx = blockIdx.x;
    if (bidx < NB_A) {
        int idx = bidx * 256 + threadIdx.x;
        int b = idx / (KK / 4), kc = idx % (KK / 4);
        int k0 = kc * 4;
        float4 v;
        if (k0 < II) v = *(const float4*)(x + (size_t)b * II + k0);
        else         v = *(const float4*)(h + (size_t)b * HH + (k0 - II));
        union { __half h[4]; uint2 u2; } p;
        p.h[0] = __float2half_rn(v.x); p.h[1] = __float2half_rn(v.y);
        p.h[2] = __float2half_rn(v.z); p.h[3] = __float2half_rn(v.w);
        *(uint2*)(g_A + (size_t)b * KK + k0) = p.u2;
    } else {
        int idx = (bidx - NB_A) * 256 + threadIdx.x;
        int n = idx / (KK / 4), kc = idx % (KK / 4);
        int u = n >> 2, g = n & 3, src = g * HH + u;
        int k0 = kc * 4;
        float4 v;
        if (k0 < II) v = *(const float4*)(Wx + (size_t)src * II + k0);
        else         v = *(const float4*)(Wh + (size_t)src * HH + (k0 - II));
        union { __half h[4]; uint2 u2; } p;
        p.h[0] = __float2half_rn(v.x); p.h[1] = __float2half_rn(v.y);
        p.h[2] = __float2half_rn(v.z); p.h[3] = __float2half_rn(v.w);
        *(uint2*)(g_W + (size_t)n * KK + k0) = p.u2;
        if (kc == 0) g_bias[n] = bx[src] + bh[src];
    }
}

// ---------------------------------------------------------------------------
// Fused GEMM + LSTM epilogue.
// CTA tile 128x128, K chunk 96, 2-stage ring (8 barriers vs 12).
// Stage layout per operand: 3 blocks of [128 rows x 64B], swizzle
// c ^= (row>>1)&3 within each 64B row (conflict-free ldsm + stores).
// 8 warps 4x2; warp tile 32x64. 2 CTAs/SM. c_in tile prefetched at start.
// ---------------------------------------------------------------------------
#define KCH 96
#define NK  (KK / KCH)        // 8
#define BLKB 8192             // one 128x64B block
#define TILEB (3 * BLKB)      // 24576 per operand per stage
#define STG  (2 * TILEB)      // 49152 per stage (A + B)
#define NSTAGE 2
#define C_OFF (NSTAGE * STG)  // 98304
#define SMEM_DYN (C_OFF + 16384)  // 114688

#define SWZ(row, c) ((((c) ^ (((row) >> 1) & 3)) << 4))

__global__ void __launch_bounds__(256, 2)
lstm_gemm(const float* __restrict__ c_in, float* __restrict__ out) {
    extern __shared__ __align__(16) unsigned char smem[];
    __shared__ float bias_s[128];

    const int tid  = threadIdx.x;
    const int warp = tid >> 5, lane = tid & 31;
    const int wm = warp >> 1, wn = warp & 1;       // 4x2 warp grid
    const int mBase = blockIdx.y * 128;
    const int nBase = blockIdx.x * 128;

    const uint32_t sbase = (uint32_t)__cvta_generic_to_shared(smem);
    if (tid < 128) bias_s[tid] = g_bias[nBase + tid];

    float acc[2][8][4];
#pragma unroll
    for (int mi = 0; mi < 2; mi++)
#pragma unroll
        for (int ni = 0; ni < 8; ni++)
#pragma unroll
            for (int d = 0; d < 4; d++) acc[mi][ni][d] = 0.f;

    const __half* gAp = g_A + (size_t)mBase * KK;
    const __half* gWp = g_W + (size_t)nBase * KK;

    // 3072 16B-chunks per stage (A: j 0-5, B: j 6-11), 12 per thread.
    auto load_stage = [&](int kt, int stage) {
        uint32_t so = sbase + stage * STG;
#pragma unroll
        for (int j = 0; j < 12; j++) {
            int idx = tid + j * 256;
            int isB = (j >= 6);
            int rem = idx - isB * 1536;
            int blk = rem >> 9;
            int row = (rem >> 2) & 127;
            int c   = rem & 3;
            const __half* src = (isB ? gWp : gAp)
                              + (size_t)row * KK + kt * KCH + blk * 32 + c * 8;
            cp_async16(so + isB * TILEB + blk * BLKB + row * 64 + SWZ(row, c), src);
        }
    };

    // Prefetch c_in tile: 128 rows x 32 f32 = 16KB (1024 chunks, 4/thread).
#pragma unroll
    for (int j = 0; j < 4; j++) {
        int idx = tid + j * 256;
        int row = idx >> 3, ch = idx & 7;
        cp_async16(sbase + C_OFF + row * 128 + ch * 16,
                   c_in + (size_t)(mBase + row) * HH + (nBase >> 2) + ch * 4);
    }
    load_stage(0, 0);
    asm volatile("cp.async.commit_group;\n");

    const int koff = warp & 3;     // stagger k16-step start across SMSP warps

    for (int kt = 0; kt < NK; kt++) {
        asm volatile("cp.async.wait_group 0;\n");
        __syncthreads();           // all warps done with the other stage

        const uint32_t so = sbase + (kt & 1) * STG;
#pragma unroll
        for (int ksi = 0; ksi < 6; ksi++) {        // six k16 steps per chunk
            int ks = ksi + koff; if (ks >= 6) ks -= 6;
            const int blk = ks >> 1, kk = ks & 1;
            uint32_t a_regs[2][4];
#pragma unroll
            for (int mi = 0; mi < 2; mi++) {
                int row = wm * 32 + mi * 16 + (lane & 15);
                int c   = kk * 2 + (lane >> 4);
                ldsm_x4(a_regs[mi], so + blk * BLKB + row * 64 + SWZ(row, c));
            }
            uint32_t b_regs[8][2];
#pragma unroll
            for (int p = 0; p < 4; p++) {          // each x4 covers two n-tiles
                int nrow = wn * 64 + p * 16 + ((lane >> 4) << 3) + (lane & 7);
                int c    = kk * 2 + ((lane >> 3) & 1);
                uint32_t r[4];
                ldsm_x4(r, so + TILEB + blk * BLKB + nrow * 64 + SWZ(nrow, c));
                b_regs[2 * p][0] = r[0]; b_regs[2 * p][1] = r[1];
                b_regs[2 * p + 1][0] = r[2]; b_regs[2 * p + 1][1] = r[3];
            }
#pragma unroll
            for (int mi = 0; mi < 2; mi++)
#pragma unroll
                for (int ni = 0; ni < 8; ni++)
                    mma16816(acc[mi][ni], a_regs[mi], b_regs[ni]);

            // Refill the other stage after the first k16 step: safe because
            // this iteration's barrier proved all warps finished consuming it.
            if (ksi == 0 && kt + 1 < NK) {
                load_stage(kt + 1, (kt + 1) & 1);
                asm volatile("cp.async.commit_group;\n");
            }
        }
    }

    // ---- Fused LSTM epilogue (two 64-row phases through smem) ----
    float* egs = (float*)smem;                      // [64][130] = 33280 B
    const float* c_s = (const float*)(smem + C_OFF);
#pragma unroll 1
    for (int half = 0; half < 2; half++) {
        __syncthreads();
        if ((wm >> 1) == half) {
            int rb = (wm & 1) * 32;
#pragma unroll
            for (int mi = 0; mi < 2; mi++)
#pragma unroll
                for (int ni = 0; ni < 8; ni++) {
                    int r = rb + mi * 16 + (lane >> 2);
                    int col = wn * 64 + ni * 8 + ((lane & 3) << 1);
                    egs[r * 130 + col]           = acc[mi][ni][0];
                    egs[r * 130 + col + 1]       = acc[mi][ni][1];
                    egs[(r + 8) * 130 + col]     = acc[mi][ni][2];
                    egs[(r + 8) * 130 + col + 1] = acc[mi][ni][3];
                }
        }
        __syncthreads();
#pragma unroll
        for (int i = 0; i < 8; i++) {
            int item = tid + i * 256;               // 2048 (row, hidden) items
            int ml = item >> 5, u = item & 31;
            float gi = egs[ml * 130 + 4 * u]     + bias_s[4 * u];
            float gf = egs[ml * 130 + 4 * u + 1] + bias_s[4 * u + 1];
            float go = egs[ml * 130 + 4 * u + 2] + bias_s[4 * u + 2];
            float gc = egs[ml * 130 + 4 * u + 3] + bias_s[4 * u + 3];
            float it = 1.f / (1.f + __expf(-gi));
            float ft = 1.f / (1.f + __expf(-gf));
            float ot = 1.f / (1.f + __expf(-go));
            float tc = 1.f - 2.f / (1.f + __expf(2.f * gc));   // tanh via MUFU
            int mg = mBase + half * 64 + ml;
            int ug = (nBase >> 2) + u;
            float cv = c_s[(half * 64 + ml) * 32 + u];
            float ct = ft * cv + it * tc;
            float ht = ot * (1.f - 2.f / (1.f + __expf(2.f * ct)));
            out[(size_t)mg * HH + ug] = ct;
            out[(size_t)BB * HH + (size_t)mg * HH + ug] = ht;
        }
    }
}

// ---------------------------------------------------------------------------
extern "C" void kernel_launch(void* const* d_in, const int* in_sizes, int n_in,
                              void* d_out, int out_size) {
    (void)in_sizes; (void)n_in; (void)out_size;
    const float* x  = (const float*)d_in[0];
    const float* h  = (const float*)d_in[1];
    const float* c  = (const float*)d_in[2];
    const float* Wx = (const float*)d_in[3];
    const float* bx = (const float*)d_in[4];
    const float* Wh = (const float*)d_in[5];
    const float* bh = (const float*)d_in[6];
    float* out = (float*)d_out;

    cudaFuncSetAttribute(lstm_gemm, cudaFuncAttributeMaxDynamicSharedMemorySize, SMEM_DYN);

    prep_all<<<NB_A + NB_W, 256>>>(x, h, Wx, bx, Wh, bh);
    lstm_gemm<<<dim3(NN / 128, BB / 128), 256, SMEM_DYN>>>(c, out);
}